// round 15
// baseline (speedup 1.0000x reference)
#include <cuda_runtime.h>
#include <cuda_fp16.h>
#include <cuda_bf16.h>
#include <math.h>
#include <stdint.h>

// ---------------- problem constants ----------------
#define BB    32
#define NN    256
#define LL    1024
#define DIMD  128
#define MODEN 8
#define HH    4
#define DHD   32
#define FFD   256
#define MQ    (BB*LL)    // 32768 rows, q path
#define MP    (BB*NN)    // 8192 rows, phi path
// ATTN_SCALE * log2(e): scores leave the S-MMA in log2 domain
#define SCALE_LOG2E 0.2550052662477581f
#define ONES_H2 0x3C003C00u

// half-weight buffer offsets
#define W_ATTNIN  0                      // 384*128 = 49152 (q-part pre-scaled)
#define W_ATTNOUT 49152                  // 128*128 = 16384
#define W_FF1     65536                  // 256*128 = 32768
#define W_FF2     98304                  // 128*256 = 32768
#define W_MLP1    131072                 // 128*1024 = 131072
#define W_MLP2    262144                 // 128*128 = 16384
#define W_TOTAL   278528

// ---------------- scratch (device globals; no allocation allowed) ----------------
__device__ float  g_X   [MQ * DIMD];
__device__ __half g_Xh  [MQ * DIMD];
__device__ float  g_X2  [MQ * DIMD];
__device__ __half g_X2h [MQ * DIMD];
__device__ __half g_QKVh[MQ * 3 * DIMD];
__device__ __half g_CTXh[MQ * DIMD];
__device__ __half g_TMPh[MQ * FFD];
__device__ float  g_PHI [MP * MODEN];
__device__ __half g_Wh  [W_TOTAL];
__device__ float  g_ABb [3 * DIMD];      // attn_in bias, q-part pre-scaled

// ---------------- helpers ----------------
__device__ __forceinline__ uint32_t smem_u32(const void* p) {
    return (uint32_t)__cvta_generic_to_shared(p);
}

__device__ __forceinline__ uint32_t f2h2(float a, float b) {
    __half2 h = __floats2half2_rn(a, b);
    return *reinterpret_cast<uint32_t*>(&h);
}

__device__ __forceinline__ float ex2f(float x) {
    float r;
    asm("ex2.approx.f32 %0, %1;" : "=f"(r) : "f"(x));
    return r;
}

__device__ __forceinline__ uint32_t h2ex2(uint32_t x) {
    uint32_t r;
    asm("ex2.approx.f16x2 %0, %1;" : "=r"(r) : "r"(x));
    return r;
}

#define LDSM4(r0,r1,r2,r3,addr) \
    asm volatile("ldmatrix.sync.aligned.m8n8.x4.shared.b16 {%0,%1,%2,%3},[%4];" \
                 : "=r"(r0),"=r"(r1),"=r"(r2),"=r"(r3) : "r"(addr))
#define LDSM4T(r0,r1,r2,r3,addr) \
    asm volatile("ldmatrix.sync.aligned.m8n8.x4.trans.shared.b16 {%0,%1,%2,%3},[%4];" \
                 : "=r"(r0),"=r"(r1),"=r"(r2),"=r"(r3) : "r"(addr))
#define MMA16816(c,a0,a1,a2,a3,b0,b1) \
    asm volatile("mma.sync.aligned.m16n8k16.row.col.f32.f16.f16.f32 " \
                 "{%0,%1,%2,%3},{%4,%5,%6,%7},{%8,%9},{%0,%1,%2,%3};" \
                 : "+f"(c[0]),"+f"(c[1]),"+f"(c[2]),"+f"(c[3]) \
                 : "r"(a0),"r"(a1),"r"(a2),"r"(a3),"r"(b0),"r"(b1))

// ---------------- one-shot weight conversion fp32 -> fp16 (q-part scaled) ----------------
__global__ void convw_kernel(const float* __restrict__ aw, const float* __restrict__ ow,
                             const float* __restrict__ f1, const float* __restrict__ f2,
                             const float* __restrict__ m1, const float* __restrict__ m2,
                             __half* __restrict__ dst) {
    int i = blockIdx.x * 256 + threadIdx.x;   // 0 .. W_TOTAL-1
    float v;
    if      (i < W_ATTNOUT) { v = aw[i]; if (i < DIMD * DIMD) v *= SCALE_LOG2E; }
    else if (i < W_FF1)     v = ow[i - W_ATTNOUT];
    else if (i < W_FF2)     v = f1[i - W_FF1];
    else if (i < W_MLP1)    v = f2[i - W_FF2];
    else if (i < W_MLP2)    v = m1[i - W_MLP1];
    else                    v = m2[i - W_MLP2];
    dst[i] = __float2half(v);
}

__global__ void biasq_kernel(const float* __restrict__ b, float* __restrict__ dst) {
    int i = threadIdx.x + blockIdx.x * 192;   // 2 blocks x 192 = 384
    if (i < 3 * DIMD) dst[i] = (i < DIMD) ? b[i] * SCALE_LOG2E : b[i];
}

// ---------------- proj_in: writes fp32 + fp16 ----------------
__global__ void proj_in_kernel(const float* __restrict__ Y,
                               const float* __restrict__ w,
                               const float* __restrict__ bias,
                               float* __restrict__ X,
                               __half* __restrict__ Xh) {
    int r = blockIdx.x;
    int b = r >> 10;
    int l = r & 1023;
    int t = threadIdx.x;              // 128
    __shared__ float xs[7];
    if (t < 7) xs[t] = Y[((size_t)b * NN + 2 + t) * LL + l];
    __syncthreads();
    float acc = bias[t];
    #pragma unroll
    for (int j = 0; j < 7; j++) acc += xs[j] * w[t * 7 + j];
    X[(size_t)r * DIMD + t]  = acc;
    Xh[(size_t)r * DIMD + t] = __float2half(acc);
}

// ---------------- fp16 tensor-core GEMM (N-tile 64), half A + half W ----------------
template<int ACT, int CHALF>
__global__ __launch_bounds__(256) void hgemm_kernel(const __half* __restrict__ A,
                                                    const __half* __restrict__ W,
                                                    const float* __restrict__ bias,
                                                    void* __restrict__ Cv,
                                                    int M, int N, int K) {
    __shared__ __half As[128][72];
    __shared__ __half Bs[64][72];
    int tid = threadIdx.x;
    int w = tid >> 5, lane = tid & 31;
    int bm = blockIdx.y * 128;
    int bn = blockIdx.x * 64;

    float acc[8][4];
    #pragma unroll
    for (int j = 0; j < 8; j++)
        #pragma unroll
        for (int c = 0; c < 4; c++) acc[j][c] = 0.f;

    for (int kt = 0; kt < K; kt += 64) {
        #pragma unroll
        for (int i = 0; i < 4; i++) {
            int idx = tid + i * 256;
            int row = idx >> 3;
            int c8  = (idx & 7) * 8;
            *(uint4*)&As[row][c8] = *(const uint4*)&A[(size_t)(bm + row) * K + kt + c8];
        }
        #pragma unroll
        for (int i = 0; i < 2; i++) {
            int idx = tid + i * 256;
            int row = idx >> 3;
            int c8  = (idx & 7) * 8;
            *(uint4*)&Bs[row][c8] = *(const uint4*)&W[(size_t)(bn + row) * K + kt + c8];
        }
        __syncthreads();

        #pragma unroll
        for (int ks2 = 0; ks2 < 2; ks2++) {
            uint32_t af[2][4];
            #pragma unroll
            for (int s = 0; s < 2; s++) {
                int row = 16 * w + (lane & 15);
                int col = ks2 * 32 + s * 16 + (lane >> 4) * 8;
                LDSM4(af[s][0], af[s][1], af[s][2], af[s][3], smem_u32(&As[row][col]));
            }
            #pragma unroll
            for (int j = 0; j < 8; j++) {
                uint32_t bf[4];
                uint32_t addr = smem_u32(&Bs[8 * j + (lane & 7)][ks2 * 32 + (lane >> 3) * 8]);
                LDSM4(bf[0], bf[1], bf[2], bf[3], addr);
                MMA16816(acc[j], af[0][0], af[0][1], af[0][2], af[0][3], bf[0], bf[1]);
                MMA16816(acc[j], af[1][0], af[1][1], af[1][2], af[1][3], bf[2], bf[3]);
            }
        }
        __syncthreads();
    }

    int row0 = bm + 16 * w + (lane >> 2);
    int row1 = row0 + 8;
    #pragma unroll
    for (int j = 0; j < 8; j++) {
        int col = bn + 8 * j + 2 * (lane & 3);
        float b0 = bias[col], b1 = bias[col + 1];
        float v0 = acc[j][0] + b0, v1 = acc[j][1] + b1;
        float v2 = acc[j][2] + b0, v3 = acc[j][3] + b1;
        if (ACT == 1) { v0 = fmaxf(v0, 0.f); v1 = fmaxf(v1, 0.f); v2 = fmaxf(v2, 0.f); v3 = fmaxf(v3, 0.f); }
        if (CHALF) {
            __half* C = (__half*)Cv;
            *(__half2*)&C[(size_t)row0 * N + col] = __floats2half2_rn(v0, v1);
            *(__half2*)&C[(size_t)row1 * N + col] = __floats2half2_rn(v2, v3);
        } else {
            float* C = (float*)Cv;
            *(float2*)&C[(size_t)row0 * N + col] = make_float2(v0, v1);
            *(float2*)&C[(size_t)row1 * N + col] = make_float2(v2, v3);
        }
    }
}

// ---------------- fused GEMM(N=128) + residual + LayerNorm [+ q projection] ----------------
template<int QPROJ>
__global__ __launch_bounds__(256) void hgemm_ln_kernel(const __half* __restrict__ A,
                                                       const __half* __restrict__ W,
                                                       const float* __restrict__ bias,
                                                       const float* __restrict__ res,
                                                       const float* __restrict__ lng,
                                                       const float* __restrict__ lnb,
                                                       float* __restrict__ Xout,
                                                       __half* __restrict__ Xhout,
                                                       const float* __restrict__ qw,
                                                       const float* __restrict__ qb,
                                                       float* __restrict__ qout,
                                                       int M, int K) {
    __shared__ __half As[128][72];
    __shared__ __half Bs[128][72];
    __shared__ float  qws[8][128];
    int tid = threadIdx.x;
    int w = tid >> 5, lane = tid & 31;
    int bm = blockIdx.x * 128;

    if (QPROJ) {
        ((float4*)qws)[tid] = ((const float4*)qw)[tid];
    }

    float acc[16][4];
    #pragma unroll
    for (int j = 0; j < 16; j++)
        #pragma unroll
        for (int c = 0; c < 4; c++) acc[j][c] = 0.f;

    for (int kt = 0; kt < K; kt += 64) {
        #pragma unroll
        for (int i = 0; i < 4; i++) {
            int idx = tid + i * 256;
            int row = idx >> 3;
            int c8  = (idx & 7) * 8;
            *(uint4*)&As[row][c8] = *(const uint4*)&A[(size_t)(bm + row) * K + kt + c8];
        }
        #pragma unroll
        for (int i = 0; i < 4; i++) {
            int idx = tid + i * 256;
            int row = idx >> 3;
            int c8  = (idx & 7) * 8;
            *(uint4*)&Bs[row][c8] = *(const uint4*)&W[(size_t)row * K + kt + c8];
        }
        __syncthreads();

        #pragma unroll
        for (int ks2 = 0; ks2 < 2; ks2++) {
            uint32_t af[2][4];
            #pragma unroll
            for (int s = 0; s < 2; s++) {
                int row = 16 * w + (lane & 15);
                int col = ks2 * 32 + s * 16 + (lane >> 4) * 8;
                LDSM4(af[s][0], af[s][1], af[s][2], af[s][3], smem_u32(&As[row][col]));
            }
            #pragma unroll
            for (int j = 0; j < 16; j++) {
                uint32_t bf[4];
                uint32_t addr = smem_u32(&Bs[8 * j + (lane & 7)][ks2 * 32 + (lane >> 3) * 8]);
                LDSM4(bf[0], bf[1], bf[2], bf[3], addr);
                MMA16816(acc[j], af[0][0], af[0][1], af[0][2], af[0][3], bf[0], bf[1]);
                MMA16816(acc[j], af[1][0], af[1][1], af[1][2], af[1][3], bf[2], bf[3]);
            }
        }
        __syncthreads();
    }

    int grow0 = bm + 16 * w + (lane >> 2);
    int grow1 = grow0 + 8;
    float s0 = 0.f, q0 = 0.f, s1 = 0.f, q1 = 0.f;
    #pragma unroll
    for (int j = 0; j < 16; j++) {
        int col = 8 * j + 2 * (lane & 3);
        float2 r0 = *(const float2*)&res[(size_t)grow0 * DIMD + col];
        float2 r1 = *(const float2*)&res[(size_t)grow1 * DIMD + col];
        float b0 = bias[col], b1 = bias[col + 1];
        acc[j][0] += b0 + r0.x;  acc[j][1] += b1 + r0.y;
        acc[j][2] += b0 + r1.x;  acc[j][3] += b1 + r1.y;
        s0 += acc[j][0] + acc[j][1];
        q0 += acc[j][0] * acc[j][0] + acc[j][1] * acc[j][1];
        s1 += acc[j][2] + acc[j][3];
        q1 += acc[j][2] * acc[j][2] + acc[j][3] * acc[j][3];
    }
    #pragma unroll
    for (int o = 1; o <= 2; o <<= 1) {
        s0 += __shfl_xor_sync(0xffffffffu, s0, o);
        q0 += __shfl_xor_sync(0xffffffffu, q0, o);
        s1 += __shfl_xor_sync(0xffffffffu, s1, o);
        q1 += __shfl_xor_sync(0xffffffffu, q1, o);
    }
    float mean0 = s0 * (1.f / 128.f), mean1 = s1 * (1.f / 128.f);
    float rs0 = rsqrtf(q0 * (1.f / 128.f) - mean0 * mean0 + 1e-5f);
    float rs1 = rsqrtf(q1 * (1.f / 128.f) - mean1 * mean1 + 1e-5f);

    if (!QPROJ) {
        #pragma unroll
        for (int j = 0; j < 16; j++) {
            int col = 8 * j + 2 * (lane & 3);
            float g0 = lng[col], g1 = lng[col + 1];
            float bb0 = lnb[col], bb1 = lnb[col + 1];
            float v0 = (acc[j][0] - mean0) * rs0 * g0 + bb0;
            float v1 = (acc[j][1] - mean0) * rs0 * g1 + bb1;
            float v2 = (acc[j][2] - mean1) * rs1 * g0 + bb0;
            float v3 = (acc[j][3] - mean1) * rs1 * g1 + bb1;
            *(float2*)&Xout[(size_t)grow0 * DIMD + col] = make_float2(v0, v1);
            *(float2*)&Xout[(size_t)grow1 * DIMD + col] = make_float2(v2, v3);
            *(__half2*)&Xhout[(size_t)grow0 * DIMD + col] = __floats2half2_rn(v0, v1);
            *(__half2*)&Xhout[(size_t)grow1 * DIMD + col] = __floats2half2_rn(v2, v3);
        }
    } else {
        float p0[8], p1[8];
        #pragma unroll
        for (int o = 0; o < 8; o++) { p0[o] = 0.f; p1[o] = 0.f; }
        #pragma unroll
        for (int j = 0; j < 16; j++) {
            int col = 8 * j + 2 * (lane & 3);
            float g0 = lng[col], g1 = lng[col + 1];
            float bb0 = lnb[col], bb1 = lnb[col + 1];
            float v0 = (acc[j][0] - mean0) * rs0 * g0 + bb0;
            float v1 = (acc[j][1] - mean0) * rs0 * g1 + bb1;
            float v2 = (acc[j][2] - mean1) * rs1 * g0 + bb0;
            float v3 = (acc[j][3] - mean1) * rs1 * g1 + bb1;
            #pragma unroll
            for (int o = 0; o < 8; o++) {
                p0[o] += v0 * qws[o][col] + v1 * qws[o][col + 1];
                p1[o] += v2 * qws[o][col] + v3 * qws[o][col + 1];
            }
        }
        #pragma unroll
        for (int o = 0; o < 8; o++) {
            #pragma unroll
            for (int m = 1; m <= 2; m <<= 1) {
                p0[o] += __shfl_xor_sync(0xffffffffu, p0[o], m);
                p1[o] += __shfl_xor_sync(0xffffffffu, p1[o], m);
            }
        }
        int k2 = lane & 3;
        float qb0 = qb[2 * k2], qb1 = qb[2 * k2 + 1];
        *(float2*)&qout[(size_t)grow0 * MODEN + 2 * k2] = make_float2(p0[2 * k2] + qb0, p0[2 * k2 + 1] + qb1);
        *(float2*)&qout[(size_t)grow1 * MODEN + 2 * k2] = make_float2(p1[2 * k2] + qb0, p1[2 * k2 + 1] + qb1);
    }
}

// ---------------- fused phi MLP ----------------
__global__ __launch_bounds__(256) void phi_fused_kernel(const float* __restrict__ Y,
                                                        const __half* __restrict__ W1h,
                                                        const float* __restrict__ b1,
                                                        const __half* __restrict__ W2h,
                                                        const float* __restrict__ b2,
                                                        const float* __restrict__ W3,
                                                        const float* __restrict__ b3,
                                                        float* __restrict__ PHI) {
    __shared__ __half As[128][72];
    __shared__ __half Bs[128][72];
    __shared__ float  w3s[8][128];
    int tid = threadIdx.x;
    int w = tid >> 5, lane = tid & 31;
    int bm = blockIdx.x * 128;

    ((float4*)w3s)[tid] = ((const float4*)W3)[tid];

    float acc[16][4];
    #pragma unroll
    for (int j = 0; j < 16; j++)
        #pragma unroll
        for (int c = 0; c < 4; c++) acc[j][c] = 0.f;

    for (int kt = 0; kt < 1024; kt += 64) {
        #pragma unroll
        for (int i = 0; i < 8; i++) {
            int idx = tid + i * 256;
            int row = idx >> 4;
            int c4  = (idx & 15) * 4;
            float4 f = *(const float4*)&Y[(size_t)(bm + row) * 1024 + kt + c4];
            __half2* d = (__half2*)&As[row][c4];
            d[0] = __floats2half2_rn(f.x, f.y);
            d[1] = __floats2half2_rn(f.z, f.w);
        }
        #pragma unroll
        for (int i = 0; i < 4; i++) {
            int idx = tid + i * 256;
            int row = idx >> 3;
            int c8  = (idx & 7) * 8;
            *(uint4*)&Bs[row][c8] = *(const uint4*)&W1h[(size_t)row * 1024 + kt + c8];
        }
        __syncthreads();
        #pragma unroll
        for (int ks2 = 0; ks2 < 2; ks2++) {
            uint32_t af[2][4];
            #pragma unroll
            for (int s = 0; s < 2; s++) {
                int row = 16 * w + (lane & 15);
                int col = ks2 * 32 + s * 16 + (lane >> 4) * 8;
                LDSM4(af[s][0], af[s][1], af[s][2], af[s][3], smem_u32(&As[row][col]));
            }
            #pragma unroll
            for (int j = 0; j < 16; j++) {
                uint32_t bf[4];
                uint32_t addr = smem_u32(&Bs[8 * j + (lane & 7)][ks2 * 32 + (lane >> 3) * 8]);
                LDSM4(bf[0], bf[1], bf[2], bf[3], addr);
                MMA16816(acc[j], af[0][0], af[0][1], af[0][2], af[0][3], bf[0], bf[1]);
                MMA16816(acc[j], af[1][0], af[1][1], af[1][2], af[1][3], bf[2], bf[3]);
            }
        }
        __syncthreads();
    }

    uint32_t af2[8][4];
    #pragma unroll
    for (int j = 0; j < 16; j++) {
        int col = 8 * j + 2 * (lane & 3);
        float b0 = b1[col], bb1 = b1[col + 1];
        acc[j][0] = tanhf(acc[j][0] + b0);
        acc[j][1] = tanhf(acc[j][1] + bb1);
        acc[j][2] = tanhf(acc[j][2] + b0);
        acc[j][3] = tanhf(acc[j][3] + bb1);
    }
    #pragma unroll
    for (int s = 0; s < 8; s++) {
        af2[s][0] = f2h2(acc[2 * s][0],     acc[2 * s][1]);
        af2[s][1] = f2h2(acc[2 * s][2],     acc[2 * s][3]);
        af2[s][2] = f2h2(acc[2 * s + 1][0], acc[2 * s + 1][1]);
        af2[s][3] = f2h2(acc[2 * s + 1][2], acc[2 * s + 1][3]);
    }

    #pragma unroll
    for (int i = 0; i < 4; i++) {
        int idx = tid + i * 256;
        int row = idx >> 3;
        int c8  = (idx & 7) * 8;
        *(uint4*)&As[row][c8] = *(const uint4*)&W2h[(size_t)row * 128 + c8];
        *(uint4*)&Bs[row][c8] = *(const uint4*)&W2h[(size_t)row * 128 + 64 + c8];
    }
    __syncthreads();

    #pragma unroll
    for (int layer = 0; layer < 2; layer++) {
        #pragma unroll
        for (int j = 0; j < 16; j++)
            #pragma unroll
            for (int c = 0; c < 4; c++) acc[j][c] = 0.f;
        #pragma unroll
        for (int sub = 0; sub < 4; sub++) {
            int co = (sub & 1) * 32;
            #pragma unroll
            for (int j = 0; j < 16; j++) {
                uint32_t bf[4];
                uint32_t addr = (sub < 2)
                    ? smem_u32(&As[8 * j + (lane & 7)][co + (lane >> 3) * 8])
                    : smem_u32(&Bs[8 * j + (lane & 7)][co + (lane >> 3) * 8]);
                LDSM4(bf[0], bf[1], bf[2], bf[3], addr);
                MMA16816(acc[j], af2[2 * sub][0], af2[2 * sub][1], af2[2 * sub][2], af2[2 * sub][3], bf[0], bf[1]);
                MMA16816(acc[j], af2[2 * sub + 1][0], af2[2 * sub + 1][1], af2[2 * sub + 1][2], af2[2 * sub + 1][3], bf[2], bf[3]);
            }
        }
        #pragma unroll
        for (int j = 0; j < 16; j++) {
            int col = 8 * j + 2 * (lane & 3);
            float b0 = b2[col], bb1 = b2[col + 1];
            acc[j][0] = tanhf(acc[j][0] + b0);
            acc[j][1] = tanhf(acc[j][1] + bb1);
            acc[j][2] = tanhf(acc[j][2] + b0);
            acc[j][3] = tanhf(acc[j][3] + bb1);
        }
        if (layer == 0) {
            #pragma unroll
            for (int s = 0; s < 8; s++) {
                af2[s][0] = f2h2(acc[2 * s][0],     acc[2 * s][1]);
                af2[s][1] = f2h2(acc[2 * s][2],     acc[2 * s][3]);
                af2[s][2] = f2h2(acc[2 * s + 1][0], acc[2 * s + 1][1]);
                af2[s][3] = f2h2(acc[2 * s + 1][2], acc[2 * s + 1][3]);
            }
        }
    }

    float p0[8], p1[8];
    #pragma unroll
    for (int o = 0; o < 8; o++) { p0[o] = 0.f; p1[o] = 0.f; }
    #pragma unroll
    for (int j = 0; j < 16; j++) {
        int col = 8 * j + 2 * (lane & 3);
        #pragma unroll
        for (int o = 0; o < 8; o++) {
            p0[o] += acc[j][0] * w3s[o][col] + acc[j][1] * w3s[o][col + 1];
            p1[o] += acc[j][2] * w3s[o][col] + acc[j][3] * w3s[o][col + 1];
        }
    }
    #pragma unroll
    for (int o = 0; o < 8; o++) {
        #pragma unroll
        for (int m = 1; m <= 2; m <<= 1) {
            p0[o] += __shfl_xor_sync(0xffffffffu, p0[o], m);
            p1[o] += __shfl_xor_sync(0xffffffffu, p1[o], m);
        }
    }
    int grow0 = bm + 16 * w + (lane >> 2);
    int grow1 = grow0 + 8;
    int k2 = lane & 3;
    float b30 = b3[2 * k2], b31 = b3[2 * k2 + 1];
    *(float2*)&PHI[(size_t)grow0 * MODEN + 2 * k2] = make_float2(p0[2 * k2] + b30, p0[2 * k2 + 1] + b31);
    *(float2*)&PHI[(size_t)grow1 * MODEN + 2 * k2] = make_float2(p1[2 * k2] + b30, p1[2 * k2 + 1] + b31);
}

// ---------------- fp16 flash attention, 128-key tiles, log2 softmax, fp16x2 exp, ones-MMA row sum ----------------
__global__ __launch_bounds__(256) void attn_mma_kernel(const __half* __restrict__ QKV,
                                                       __half* __restrict__ CTX) {
    int h = blockIdx.y;
    int b = blockIdx.z;
    int qbase = blockIdx.x * 128;
    int t = threadIdx.x;
    int w = t >> 5, lane = t & 31;

    __shared__ __half Qs[128][40];
    __shared__ __half Ks[128][40];
    __shared__ __half Vs[128][40];

    const __half* base = QKV + (size_t)b * (LL * 384);

    #pragma unroll
    for (int i = 0; i < 2; i++) {
        int idx = t + i * 256;
        int row = idx >> 2;
        int c8  = (idx & 3) * 8;
        *(uint4*)&Qs[row][c8] =
            *(const uint4*)(base + (size_t)(qbase + row) * 384 + h * 32 + c8);
    }

    int tt = t & 127;
    int koff = (t < 128) ? 128 : 256;
    uint4 pf[4];
    {
        const uint4* s = (const uint4*)(base + (size_t)tt * 384 + koff + h * 32);
        pf[0] = s[0]; pf[1] = s[1]; pf[2] = s[2]; pf[3] = s[3];
    }
    __syncthreads();

    uint32_t qa[2][4];
    {
        int qr = w * 16;
        #pragma unroll
        for (int s = 0; s < 2; s++) {
            int row = qr + (lane & 15);
            int col = s * 16 + (lane >> 4) * 8;
            LDSM4(qa[s][0], qa[s][1], qa[s][2], qa[s][3], smem_u32(&Qs[row][col]));
        }
    }

    float oacc[4][4];
    #pragma unroll
    for (int j = 0; j < 4; j++)
        #pragma unroll
        for (int c = 0; c < 4; c++) oacc[j][c] = 0.f;
    float oaccS[4] = {0.f, 0.f, 0.f, 0.f};   // row-sum accumulator (ones-MMA)
    float mrun0 = -1e30f, mrun1 = -1e30f;

    for (int kt = 0; kt < 8; kt++) {
        {
            uint4* d = (uint4*)&((t < 128) ? Ks : Vs)[tt][0];
            d[0] = pf[0]; d[1] = pf[1]; d[2] = pf[2]; d[3] = pf[3];
        }
        __syncthreads();
        if (kt < 7) {
            const uint4* s = (const uint4*)(base + (size_t)((kt + 1) * 128 + tt) * 384 + koff + h * 32);
            pf[0] = s[0]; pf[1] = s[1]; pf[2] = s[2]; pf[3] = s[3];
        }

        // ---- S = Q K^T (log2 domain) ----
        float sacc[16][4];
        #pragma unroll
        for (int j = 0; j < 16; j++)
            #pragma unroll
            for (int c = 0; c < 4; c++) sacc[j][c] = 0.f;

        #pragma unroll
        for (int j = 0; j < 16; j++) {
            uint32_t kb[4];
            uint32_t addr = smem_u32(&Ks[8 * j + (lane & 7)][(lane >> 3) * 8]);
            LDSM4(kb[0], kb[1], kb[2], kb[3], addr);
            MMA16816(sacc[j], qa[0][0], qa[0][1], qa[0][2], qa[0][3], kb[0], kb[1]);
            MMA16816(sacc[j], qa[1][0], qa[1][1], qa[1][2], qa[1][3], kb[2], kb[3]);
        }

        // ---- running max ----
        float mx0 = -1e30f, mx1 = -1e30f;
        #pragma unroll
        for (int j = 0; j < 16; j++) {
            mx0 = fmaxf(mx0, fmaxf(sacc[j][0], sacc[j][1]));
            mx1 = fmaxf(mx1, fmaxf(sacc[j][2], sacc[j][3]));
        }
        #pragma unroll
        for (int o = 1; o <= 2; o <<= 1) {
            mx0 = fmaxf(mx0, __shfl_xor_sync(0xffffffffu, mx0, o));
            mx1 = fmaxf(mx1, __shfl_xor_sync(0xffffffffu, mx1, o));
        }
        float nm0 = fmaxf(mrun0, mx0), nm1 = fmaxf(mrun1, mx1);
        float al0 = ex2f(mrun0 - nm0), al1 = ex2f(mrun1 - nm1);
        mrun0 = nm0; mrun1 = nm1;

        // ---- rescale O and row-sum ----
        #pragma unroll
        for (int j = 0; j < 4; j++) {
            oacc[j][0] *= al0; oacc[j][1] *= al0;
            oacc[j][2] *= al1; oacc[j][3] *= al1;
        }
        oaccS[0] *= al0; oaccS[1] *= al0; oaccS[2] *= al1; oaccS[3] *= al1;

        // ---- O += P V, P = ex2(s - nm) in fp16; l via ones-MMA ----
        #pragma unroll
        for (int s = 0; s < 8; s++) {
            uint32_t pa0 = h2ex2(f2h2(sacc[2 * s][0] - nm0, sacc[2 * s][1] - nm0));
            uint32_t pa1 = h2ex2(f2h2(sacc[2 * s][2] - nm1, sacc[2 * s][3] - nm1));
            uint32_t pa2 = h2ex2(f2h2(sacc[2 * s + 1][0] - nm0, sacc[2 * s + 1][1] - nm0));
            uint32_t pa3 = h2ex2(f2h2(sacc[2 * s + 1][2] - nm1, sacc[2 * s + 1][3] - nm1));
            #pragma unroll
            for (int jj = 0; jj < 2; jj++) {
                uint32_t vb[4];
                uint32_t addr = smem_u32(&Vs[16 * s + (lane & 15)][8 * (2 * jj + (lane >> 4))]);
                LDSM4T(vb[0], vb[1], vb[2], vb[3], addr);
                MMA16816(oacc[2 * jj],     pa0, pa1, pa2, pa3, vb[0], vb[1]);
                MMA16816(oacc[2 * jj + 1], pa0, pa1, pa2, pa3, vb[2], vb[3]);
            }
            MMA16816(oaccS, pa0, pa1, pa2, pa3, ONES_H2, ONES_H2);
        }
        __syncthreads();
    }

    float inv0 = 1.f / oaccS[0], inv1 = 1.f / oaccS[2];
    int r0 = qbase + w * 16 + (lane >> 2);
    __half* o0 = CTX + ((size_t)(b * LL + r0)) * DIMD + h * 32 + 2 * (lane & 3);
    __half* o1 = o0 + 8 * DIMD;
    #pragma unroll
    for (int j = 0; j < 4; j++) {
        *(__half2*)(o0 + 8 * j) = __floats2half2_rn(oacc[j][0] * inv0, oacc[j][1] * inv0);
        *(__half2*)(o1 + 8 * j) = __floats2half2_rn(oacc[j][2] * inv1, oacc[j][3] * inv1);
    }
}

// ---------------- fused per-batch maxabs + normalize ----------------
__global__ void norm_kernel(const float* __restrict__ phi, float* __restrict__ out) {
    int b = blockIdx.x;
    int n = threadIdx.x; // 256
    __shared__ float sm[256][8];
    float v[8];
    #pragma unroll
    for (int j = 0; j < 8; j++) {
        v[j] = phi[((size_t)b * NN + n) * MODEN + j];
        sm[n][j] = fabsf(v[j]);
    }
    __syncthreads();
    for (int s = 128; s > 0; s >>= 1) {
        if (n < s) {
            #pragma unroll
            for (int j = 0; j < 8; j++) sm[n][j] = fmaxf(sm[n][j], sm[n + s][j]);
        }
        __syncthreads();
    }
    #pragma unroll
    for (int j = 0; j < 8; j++)
        out[((size_t)b * NN + n) * MODEN + j] = v[j] / sm[0][j];
}

// ---------------- launch ----------------
extern "C" void kernel_launch(void* const* d_in, const int* in_sizes, int n_in,
                              void* d_out, int out_size) {
    (void)in_sizes; (void)n_in; (void)out_size;
    const float* acc_Y      = (const float*)d_in[0];
    const float* proj_in_w  = (const float*)d_in[2];
    const float* proj_in_b  = (const float*)d_in[3];
    const float* attn_in_w  = (const float*)d_in[4];
    const float* attn_in_b  = (const float*)d_in[5];
    const float* attn_out_w = (const float*)d_in[6];
    const float* attn_out_b = (const float*)d_in[7];
    const float* ln1_g      = (const float*)d_in[8];
    const float* ln1_b      = (const float*)d_in[9];
    const float* ff1_w      = (const float*)d_in[10];
    const float* ff1_b      = (const float*)d_in[11];
    const float* ff2_w      = (const float*)d_in[12];
    const float* ff2_b      = (const float*)d_in[13];
    const float* ln2_g      = (const float*)d_in[14];
    const float* ln2_b      = (const float*)d_in[15];
    const float* proj_out_w = (const float*)d_in[16];
    const float* proj_out_b = (const float*)d_in[17];
    const float* mlp1_w     = (const float*)d_in[18];
    const float* mlp1_b     = (const float*)d_in[19];
    const float* mlp2_w     = (const float*)d_in[20];
    const float* mlp2_b     = (const float*)d_in[21];
    const float* mlp3_w     = (const float*)d_in[22];
    const float* mlp3_b     = (const float*)d_in[23];
    float* out = (float*)d_out;

    float  *pX, *pX2, *pPHI, *pABb;
    __half *pXh, *pX2h, *pQKVh, *pCTXh, *pTMPh, *pWh;
    cudaGetSymbolAddress((void**)&pX,    g_X);
    cudaGetSymbolAddress((void**)&pXh,   g_Xh);
    cudaGetSymbolAddress((void**)&pX2,   g_X2);
    cudaGetSymbolAddress((void**)&pX2h,  g_X2h);
    cudaGetSymbolAddress((void**)&pQKVh, g_QKVh);
    cudaGetSymbolAddress((void**)&pCTXh, g_CTXh);
    cudaGetSymbolAddress((void**)&pTMPh, g_TMPh);
    cudaGetSymbolAddress((void**)&pPHI,  g_PHI);
    cudaGetSymbolAddress((void**)&pWh,   g_Wh);
    cudaGetSymbolAddress((void**)&pABb,  g_ABb);

    convw_kernel<<<W_TOTAL / 256, 256>>>(attn_in_w, attn_out_w, ff1_w, ff2_w, mlp1_w, mlp2_w, pWh);
    biasq_kernel<<<2, 192>>>(attn_in_b, pABb);

    // ===== q path =====
    proj_in_kernel<<<MQ, 128>>>(acc_Y, proj_in_w, proj_in_b, pX, pXh);
    hgemm_kernel<0,1><<<dim3(6, MQ / 128), 256>>>(pXh, pWh + W_ATTNIN, pABb, pQKVh, MQ, 384, 128);
    attn_mma_kernel<<<dim3(LL / 128, HH, BB), 256>>>(pQKVh, pCTXh);
    hgemm_ln_kernel<0><<<MQ / 128, 256>>>(pCTXh, pWh + W_ATTNOUT, attn_out_b, pX, ln1_g, ln1_b,
                                          pX2, pX2h, nullptr, nullptr, nullptr, MQ, 128);
    hgemm_kernel<1,1><<<dim3(4, MQ / 128), 256>>>(pX2h, pWh + W_FF1, ff1_b, pTMPh, MQ, 256, 128);
    hgemm_ln_kernel<1><<<MQ / 128, 256>>>(pTMPh, pWh + W_FF2, ff2_b, pX2, ln2_g, ln2_b,
                                          nullptr, nullptr, proj_out_w, proj_out_b, out, MQ, 256);

    // ===== phi path (fused) =====
    phi_fused_kernel<<<MP / 128, 256>>>(acc_Y, pWh + W_MLP1, mlp1_b, pWh + W_MLP2, mlp2_b,
                                        mlp3_w, mlp3_b, pPHI);
    norm_kernel<<<BB, 256>>>(pPHI, out + MQ * MODEN);
}

// round 16
// speedup vs baseline: 1.0908x; 1.0908x over previous
#include <cuda_runtime.h>
#include <cuda_fp16.h>
#include <cuda_bf16.h>
#include <math.h>
#include <stdint.h>

// ---------------- problem constants ----------------
#define BB    32
#define NN    256
#define LL    1024
#define DIMD  128
#define MODEN 8
#define HH    4
#define DHD   32
#define FFD   256
#define MQ    (BB*LL)    // 32768 rows, q path
#define MP    (BB*NN)    // 8192 rows, phi path
// ATTN_SCALE * log2(e): scores leave the S-MMA in log2 domain
#define SCALE_LOG2E 0.2550052662477581f

// half-weight buffer offsets
#define W_ATTNIN  0                      // 384*128 = 49152 (q-part pre-scaled)
#define W_ATTNOUT 49152                  // 128*128 = 16384
#define W_FF1     65536                  // 256*128 = 32768
#define W_FF2     98304                  // 128*256 = 32768
#define W_MLP1    131072                 // 128*1024 = 131072
#define W_MLP2    262144                 // 128*128 = 16384
#define W_TOTAL   278528

// ---------------- scratch (device globals; no allocation allowed) ----------------
__device__ float  g_X   [MQ * DIMD];
__device__ __half g_Xh  [MQ * DIMD];
__device__ float  g_X2  [MQ * DIMD];
__device__ __half g_X2h [MQ * DIMD];
__device__ __half g_QKVh[MQ * 3 * DIMD];
__device__ __half g_CTXh[MQ * DIMD];
__device__ __half g_TMPh[MQ * FFD];
__device__ float  g_PHI [MP * MODEN];
__device__ __half g_Wh  [W_TOTAL];
__device__ float  g_ABb [3 * DIMD];      // attn_in bias, q-part pre-scaled

// ---------------- helpers ----------------
__device__ __forceinline__ uint32_t smem_u32(const void* p) {
    return (uint32_t)__cvta_generic_to_shared(p);
}

__device__ __forceinline__ uint32_t f2h2(float a, float b) {
    __half2 h = __floats2half2_rn(a, b);
    return *reinterpret_cast<uint32_t*>(&h);
}

__device__ __forceinline__ float ex2f(float x) {
    float r;
    asm("ex2.approx.f32 %0, %1;" : "=f"(r) : "f"(x));
    return r;
}

#define LDSM4(r0,r1,r2,r3,addr) \
    asm volatile("ldmatrix.sync.aligned.m8n8.x4.shared.b16 {%0,%1,%2,%3},[%4];" \
                 : "=r"(r0),"=r"(r1),"=r"(r2),"=r"(r3) : "r"(addr))
#define LDSM4T(r0,r1,r2,r3,addr) \
    asm volatile("ldmatrix.sync.aligned.m8n8.x4.trans.shared.b16 {%0,%1,%2,%3},[%4];" \
                 : "=r"(r0),"=r"(r1),"=r"(r2),"=r"(r3) : "r"(addr))
#define MMA16816(c,a0,a1,a2,a3,b0,b1) \
    asm volatile("mma.sync.aligned.m16n8k16.row.col.f32.f16.f16.f32 " \
                 "{%0,%1,%2,%3},{%4,%5,%6,%7},{%8,%9},{%0,%1,%2,%3};" \
                 : "+f"(c[0]),"+f"(c[1]),"+f"(c[2]),"+f"(c[3]) \
                 : "r"(a0),"r"(a1),"r"(a2),"r"(a3),"r"(b0),"r"(b1))

// ---------------- one-shot weight conversion fp32 -> fp16 (q-part scaled) ----------------
__global__ void convw_kernel(const float* __restrict__ aw, const float* __restrict__ ow,
                             const float* __restrict__ f1, const float* __restrict__ f2,
                             const float* __restrict__ m1, const float* __restrict__ m2,
                             __half* __restrict__ dst) {
    int i = blockIdx.x * 256 + threadIdx.x;   // 0 .. W_TOTAL-1
    float v;
    if      (i < W_ATTNOUT) { v = aw[i]; if (i < DIMD * DIMD) v *= SCALE_LOG2E; }
    else if (i < W_FF1)     v = ow[i - W_ATTNOUT];
    else if (i < W_FF2)     v = f1[i - W_FF1];
    else if (i < W_MLP1)    v = f2[i - W_FF2];
    else if (i < W_MLP2)    v = m1[i - W_MLP1];
    else                    v = m2[i - W_MLP2];
    dst[i] = __float2half(v);
}

__global__ void biasq_kernel(const float* __restrict__ b, float* __restrict__ dst) {
    int i = threadIdx.x + blockIdx.x * 192;   // 2 blocks x 192 = 384
    if (i < 3 * DIMD) dst[i] = (i < DIMD) ? b[i] * SCALE_LOG2E : b[i];
}

// ---------------- proj_in: writes fp32 + fp16 ----------------
__global__ void proj_in_kernel(const float* __restrict__ Y,
                               const float* __restrict__ w,
                               const float* __restrict__ bias,
                               float* __restrict__ X,
                               __half* __restrict__ Xh) {
    int r = blockIdx.x;
    int b = r >> 10;
    int l = r & 1023;
    int t = threadIdx.x;              // 128
    __shared__ float xs[7];
    if (t < 7) xs[t] = Y[((size_t)b * NN + 2 + t) * LL + l];
    __syncthreads();
    float acc = bias[t];
    #pragma unroll
    for (int j = 0; j < 7; j++) acc += xs[j] * w[t * 7 + j];
    X[(size_t)r * DIMD + t]  = acc;
    Xh[(size_t)r * DIMD + t] = __float2half(acc);
}

// ---------------- fp16 tensor-core GEMM (N-tile 64), register-prefetch pipelined ----------------
template<int ACT, int CHALF>
__global__ __launch_bounds__(256) void hgemm_kernel(const __half* __restrict__ A,
                                                    const __half* __restrict__ W,
                                                    const float* __restrict__ bias,
                                                    void* __restrict__ Cv,
                                                    int M, int N, int K) {
    __shared__ __half As[128][72];
    __shared__ __half Bs[64][72];
    int tid = threadIdx.x;
    int w = tid >> 5, lane = tid & 31;
    int bm = blockIdx.y * 128;
    int bn = blockIdx.x * 64;

    float acc[8][4];
    #pragma unroll
    for (int j = 0; j < 8; j++)
        #pragma unroll
        for (int c = 0; c < 4; c++) acc[j][c] = 0.f;

    // thread's fixed load slots: A rows (tid>>3)+{0,32,64,96}, col (tid&7)*8 ; W rows (tid>>3)+{0,32}
    int lrow = tid >> 3;
    int lc8  = (tid & 7) * 8;

    // ---- preload tile 0 ----
    uint4 pa[4], pw[2];
    #pragma unroll
    for (int i = 0; i < 4; i++)
        pa[i] = *(const uint4*)&A[(size_t)(bm + lrow + 32 * i) * K + lc8];
    #pragma unroll
    for (int i = 0; i < 2; i++)
        pw[i] = *(const uint4*)&W[(size_t)(bn + lrow + 32 * i) * K + lc8];

    int nchunk = K >> 6;
    for (int kc = 0; kc < nchunk; kc++) {
        // commit prefetched tile
        #pragma unroll
        for (int i = 0; i < 4; i++) *(uint4*)&As[lrow + 32 * i][lc8] = pa[i];
        #pragma unroll
        for (int i = 0; i < 2; i++) *(uint4*)&Bs[lrow + 32 * i][lc8] = pw[i];
        __syncthreads();
        // prefetch next (overlaps with compute)
        if (kc + 1 < nchunk) {
            int kt = (kc + 1) * 64;
            #pragma unroll
            for (int i = 0; i < 4; i++)
                pa[i] = *(const uint4*)&A[(size_t)(bm + lrow + 32 * i) * K + kt + lc8];
            #pragma unroll
            for (int i = 0; i < 2; i++)
                pw[i] = *(const uint4*)&W[(size_t)(bn + lrow + 32 * i) * K + kt + lc8];
        }

        #pragma unroll
        for (int ks2 = 0; ks2 < 2; ks2++) {
            uint32_t af[2][4];
            #pragma unroll
            for (int s = 0; s < 2; s++) {
                int row = 16 * w + (lane & 15);
                int col = ks2 * 32 + s * 16 + (lane >> 4) * 8;
                LDSM4(af[s][0], af[s][1], af[s][2], af[s][3], smem_u32(&As[row][col]));
            }
            #pragma unroll
            for (int j = 0; j < 8; j++) {
                uint32_t bf[4];
                uint32_t addr = smem_u32(&Bs[8 * j + (lane & 7)][ks2 * 32 + (lane >> 3) * 8]);
                LDSM4(bf[0], bf[1], bf[2], bf[3], addr);
                MMA16816(acc[j], af[0][0], af[0][1], af[0][2], af[0][3], bf[0], bf[1]);
                MMA16816(acc[j], af[1][0], af[1][1], af[1][2], af[1][3], bf[2], bf[3]);
            }
        }
        __syncthreads();
    }

    int row0 = bm + 16 * w + (lane >> 2);
    int row1 = row0 + 8;
    #pragma unroll
    for (int j = 0; j < 8; j++) {
        int col = bn + 8 * j + 2 * (lane & 3);
        float b0 = bias[col], b1 = bias[col + 1];
        float v0 = acc[j][0] + b0, v1 = acc[j][1] + b1;
        float v2 = acc[j][2] + b0, v3 = acc[j][3] + b1;
        if (ACT == 1) { v0 = fmaxf(v0, 0.f); v1 = fmaxf(v1, 0.f); v2 = fmaxf(v2, 0.f); v3 = fmaxf(v3, 0.f); }
        if (CHALF) {
            __half* C = (__half*)Cv;
            *(__half2*)&C[(size_t)row0 * N + col] = __floats2half2_rn(v0, v1);
            *(__half2*)&C[(size_t)row1 * N + col] = __floats2half2_rn(v2, v3);
        } else {
            float* C = (float*)Cv;
            *(float2*)&C[(size_t)row0 * N + col] = make_float2(v0, v1);
            *(float2*)&C[(size_t)row1 * N + col] = make_float2(v2, v3);
        }
    }
}

// ---------------- fused GEMM(N=128) + residual + LayerNorm [+ q projection] ----------------
template<int QPROJ>
__global__ __launch_bounds__(256) void hgemm_ln_kernel(const __half* __restrict__ A,
                                                       const __half* __restrict__ W,
                                                       const float* __restrict__ bias,
                                                       const float* __restrict__ res,
                                                       const float* __restrict__ lng,
                                                       const float* __restrict__ lnb,
                                                       float* __restrict__ Xout,
                                                       __half* __restrict__ Xhout,
                                                       const float* __restrict__ qw,
                                                       const float* __restrict__ qb,
                                                       float* __restrict__ qout,
                                                       int M, int K) {
    __shared__ __half As[128][72];
    __shared__ __half Bs[128][72];
    __shared__ float  qws[8][128];
    int tid = threadIdx.x;
    int w = tid >> 5, lane = tid & 31;
    int bm = blockIdx.x * 128;

    if (QPROJ) {
        ((float4*)qws)[tid] = ((const float4*)qw)[tid];
    }

    float acc[16][4];
    #pragma unroll
    for (int j = 0; j < 16; j++)
        #pragma unroll
        for (int c = 0; c < 4; c++) acc[j][c] = 0.f;

    for (int kt = 0; kt < K; kt += 64) {
        #pragma unroll
        for (int i = 0; i < 4; i++) {
            int idx = tid + i * 256;
            int row = idx >> 3;
            int c8  = (idx & 7) * 8;
            *(uint4*)&As[row][c8] = *(const uint4*)&A[(size_t)(bm + row) * K + kt + c8];
        }
        #pragma unroll
        for (int i = 0; i < 4; i++) {
            int idx = tid + i * 256;
            int row = idx >> 3;
            int c8  = (idx & 7) * 8;
            *(uint4*)&Bs[row][c8] = *(const uint4*)&W[(size_t)row * K + kt + c8];
        }
        __syncthreads();

        #pragma unroll
        for (int ks2 = 0; ks2 < 2; ks2++) {
            uint32_t af[2][4];
            #pragma unroll
            for (int s = 0; s < 2; s++) {
                int row = 16 * w + (lane & 15);
                int col = ks2 * 32 + s * 16 + (lane >> 4) * 8;
                LDSM4(af[s][0], af[s][1], af[s][2], af[s][3], smem_u32(&As[row][col]));
            }
            #pragma unroll
            for (int j = 0; j < 16; j++) {
                uint32_t bf[4];
                uint32_t addr = smem_u32(&Bs[8 * j + (lane & 7)][ks2 * 32 + (lane >> 3) * 8]);
                LDSM4(bf[0], bf[1], bf[2], bf[3], addr);
                MMA16816(acc[j], af[0][0], af[0][1], af[0][2], af[0][3], bf[0], bf[1]);
                MMA16816(acc[j], af[1][0], af[1][1], af[1][2], af[1][3], bf[2], bf[3]);
            }
        }
        __syncthreads();
    }

    int grow0 = bm + 16 * w + (lane >> 2);
    int grow1 = grow0 + 8;
    float s0 = 0.f, q0 = 0.f, s1 = 0.f, q1 = 0.f;
    #pragma unroll
    for (int j = 0; j < 16; j++) {
        int col = 8 * j + 2 * (lane & 3);
        float2 r0 = *(const float2*)&res[(size_t)grow0 * DIMD + col];
        float2 r1 = *(const float2*)&res[(size_t)grow1 * DIMD + col];
        float b0 = bias[col], b1 = bias[col + 1];
        acc[j][0] += b0 + r0.x;  acc[j][1] += b1 + r0.y;
        acc[j][2] += b0 + r1.x;  acc[j][3] += b1 + r1.y;
        s0 += acc[j][0] + acc[j][1];
        q0 += acc[j][0] * acc[j][0] + acc[j][1] * acc[j][1];
        s1 += acc[j][2] + acc[j][3];
        q1 += acc[j][2] * acc[j][2] + acc[j][3] * acc[j][3];
    }
    #pragma unroll
    for (int o = 1; o <= 2; o <<= 1) {
        s0 += __shfl_xor_sync(0xffffffffu, s0, o);
        q0 += __shfl_xor_sync(0xffffffffu, q0, o);
        s1 += __shfl_xor_sync(0xffffffffu, s1, o);
        q1 += __shfl_xor_sync(0xffffffffu, q1, o);
    }
    float mean0 = s0 * (1.f / 128.f), mean1 = s1 * (1.f / 128.f);
    float rs0 = rsqrtf(q0 * (1.f / 128.f) - mean0 * mean0 + 1e-5f);
    float rs1 = rsqrtf(q1 * (1.f / 128.f) - mean1 * mean1 + 1e-5f);

    if (!QPROJ) {
        #pragma unroll
        for (int j = 0; j < 16; j++) {
            int col = 8 * j + 2 * (lane & 3);
            float g0 = lng[col], g1 = lng[col + 1];
            float bb0 = lnb[col], bb1 = lnb[col + 1];
            float v0 = (acc[j][0] - mean0) * rs0 * g0 + bb0;
            float v1 = (acc[j][1] - mean0) * rs0 * g1 + bb1;
            float v2 = (acc[j][2] - mean1) * rs1 * g0 + bb0;
            float v3 = (acc[j][3] - mean1) * rs1 * g1 + bb1;
            *(float2*)&Xout[(size_t)grow0 * DIMD + col] = make_float2(v0, v1);
            *(float2*)&Xout[(size_t)grow1 * DIMD + col] = make_float2(v2, v3);
            *(__half2*)&Xhout[(size_t)grow0 * DIMD + col] = __floats2half2_rn(v0, v1);
            *(__half2*)&Xhout[(size_t)grow1 * DIMD + col] = __floats2half2_rn(v2, v3);
        }
    } else {
        float p0[8], p1[8];
        #pragma unroll
        for (int o = 0; o < 8; o++) { p0[o] = 0.f; p1[o] = 0.f; }
        #pragma unroll
        for (int j = 0; j < 16; j++) {
            int col = 8 * j + 2 * (lane & 3);
            float g0 = lng[col], g1 = lng[col + 1];
            float bb0 = lnb[col], bb1 = lnb[col + 1];
            float v0 = (acc[j][0] - mean0) * rs0 * g0 + bb0;
            float v1 = (acc[j][1] - mean0) * rs0 * g1 + bb1;
            float v2 = (acc[j][2] - mean1) * rs1 * g0 + bb0;
            float v3 = (acc[j][3] - mean1) * rs1 * g1 + bb1;
            #pragma unroll
            for (int o = 0; o < 8; o++) {
                p0[o] += v0 * qws[o][col] + v1 * qws[o][col + 1];
                p1[o] += v2 * qws[o][col] + v3 * qws[o][col + 1];
            }
        }
        #pragma unroll
        for (int o = 0; o < 8; o++) {
            #pragma unroll
            for (int m = 1; m <= 2; m <<= 1) {
                p0[o] += __shfl_xor_sync(0xffffffffu, p0[o], m);
                p1[o] += __shfl_xor_sync(0xffffffffu, p1[o], m);
            }
        }
        int k2 = lane & 3;
        float qb0 = qb[2 * k2], qb1 = qb[2 * k2 + 1];
        *(float2*)&qout[(size_t)grow0 * MODEN + 2 * k2] = make_float2(p0[2 * k2] + qb0, p0[2 * k2 + 1] + qb1);
        *(float2*)&qout[(size_t)grow1 * MODEN + 2 * k2] = make_float2(p1[2 * k2] + qb0, p1[2 * k2 + 1] + qb1);
    }
}

// ---------------- fused phi MLP ----------------
__global__ __launch_bounds__(256) void phi_fused_kernel(const float* __restrict__ Y,
                                                        const __half* __restrict__ W1h,
                                                        const float* __restrict__ b1,
                                                        const __half* __restrict__ W2h,
                                                        const float* __restrict__ b2,
                                                        const float* __restrict__ W3,
                                                        const float* __restrict__ b3,
                                                        float* __restrict__ PHI) {
    __shared__ __half As[128][72];
    __shared__ __half Bs[128][72];
    __shared__ float  w3s[8][128];
    int tid = threadIdx.x;
    int w = tid >> 5, lane = tid & 31;
    int bm = blockIdx.x * 128;

    ((float4*)w3s)[tid] = ((const float4*)W3)[tid];

    float acc[16][4];
    #pragma unroll
    for (int j = 0; j < 16; j++)
        #pragma unroll
        for (int c = 0; c < 4; c++) acc[j][c] = 0.f;

    for (int kt = 0; kt < 1024; kt += 64) {
        #pragma unroll
        for (int i = 0; i < 8; i++) {
            int idx = tid + i * 256;
            int row = idx >> 4;
            int c4  = (idx & 15) * 4;
            float4 f = *(const float4*)&Y[(size_t)(bm + row) * 1024 + kt + c4];
            __half2* d = (__half2*)&As[row][c4];
            d[0] = __floats2half2_rn(f.x, f.y);
            d[1] = __floats2half2_rn(f.z, f.w);
        }
        #pragma unroll
        for (int i = 0; i < 4; i++) {
            int idx = tid + i * 256;
            int row = idx >> 3;
            int c8  = (idx & 7) * 8;
            *(uint4*)&Bs[row][c8] = *(const uint4*)&W1h[(size_t)row * 1024 + kt + c8];
        }
        __syncthreads();
        #pragma unroll
        for (int ks2 = 0; ks2 < 2; ks2++) {
            uint32_t af[2][4];
            #pragma unroll
            for (int s = 0; s < 2; s++) {
                int row = 16 * w + (lane & 15);
                int col = ks2 * 32 + s * 16 + (lane >> 4) * 8;
                LDSM4(af[s][0], af[s][1], af[s][2], af[s][3], smem_u32(&As[row][col]));
            }
            #pragma unroll
            for (int j = 0; j < 16; j++) {
                uint32_t bf[4];
                uint32_t addr = smem_u32(&Bs[8 * j + (lane & 7)][ks2 * 32 + (lane >> 3) * 8]);
                LDSM4(bf[0], bf[1], bf[2], bf[3], addr);
                MMA16816(acc[j], af[0][0], af[0][1], af[0][2], af[0][3], bf[0], bf[1]);
                MMA16816(acc[j], af[1][0], af[1][1], af[1][2], af[1][3], bf[2], bf[3]);
            }
        }
        __syncthreads();
    }

    uint32_t af2[8][4];
    #pragma unroll
    for (int j = 0; j < 16; j++) {
        int col = 8 * j + 2 * (lane & 3);
        float b0 = b1[col], bb1 = b1[col + 1];
        acc[j][0] = tanhf(acc[j][0] + b0);
        acc[j][1] = tanhf(acc[j][1] + bb1);
        acc[j][2] = tanhf(acc[j][2] + b0);
        acc[j][3] = tanhf(acc[j][3] + bb1);
    }
    #pragma unroll
    for (int s = 0; s < 8; s++) {
        af2[s][0] = f2h2(acc[2 * s][0],     acc[2 * s][1]);
        af2[s][1] = f2h2(acc[2 * s][2],     acc[2 * s][3]);
        af2[s][2] = f2h2(acc[2 * s + 1][0], acc[2 * s + 1][1]);
        af2[s][3] = f2h2(acc[2 * s + 1][2], acc[2 * s + 1][3]);
    }

    #pragma unroll
    for (int i = 0; i < 4; i++) {
        int idx = tid + i * 256;
        int row = idx >> 3;
        int c8  = (idx & 7) * 8;
        *(uint4*)&As[row][c8] = *(const uint4*)&W2h[(size_t)row * 128 + c8];
        *(uint4*)&Bs[row][c8] = *(const uint4*)&W2h[(size_t)row * 128 + 64 + c8];
    }
    __syncthreads();

    #pragma unroll
    for (int layer = 0; layer < 2; layer++) {
        #pragma unroll
        for (int j = 0; j < 16; j++)
            #pragma unroll
            for (int c = 0; c < 4; c++) acc[j][c] = 0.f;
        #pragma unroll
        for (int sub = 0; sub < 4; sub++) {
            int co = (sub & 1) * 32;
            #pragma unroll
            for (int j = 0; j < 16; j++) {
                uint32_t bf[4];
                uint32_t addr = (sub < 2)
                    ? smem_u32(&As[8 * j + (lane & 7)][co + (lane >> 3) * 8])
                    : smem_u32(&Bs[8 * j + (lane & 7)][co + (lane >> 3) * 8]);
                LDSM4(bf[0], bf[1], bf[2], bf[3], addr);
                MMA16816(acc[j], af2[2 * sub][0], af2[2 * sub][1], af2[2 * sub][2], af2[2 * sub][3], bf[0], bf[1]);
                MMA16816(acc[j], af2[2 * sub + 1][0], af2[2 * sub + 1][1], af2[2 * sub + 1][2], af2[2 * sub + 1][3], bf[2], bf[3]);
            }
        }
        #pragma unroll
        for (int j = 0; j < 16; j++) {
            int col = 8 * j + 2 * (lane & 3);
            float b0 = b2[col], bb1 = b2[col + 1];
            acc[j][0] = tanhf(acc[j][0] + b0);
            acc[j][1] = tanhf(acc[j][1] + bb1);
            acc[j][2] = tanhf(acc[j][2] + b0);
            acc[j][3] = tanhf(acc[j][3] + bb1);
        }
        if (layer == 0) {
            #pragma unroll
            for (int s = 0; s < 8; s++) {
                af2[s][0] = f2h2(acc[2 * s][0],     acc[2 * s][1]);
                af2[s][1] = f2h2(acc[2 * s][2],     acc[2 * s][3]);
                af2[s][2] = f2h2(acc[2 * s + 1][0], acc[2 * s + 1][1]);
                af2[s][3] = f2h2(acc[2 * s + 1][2], acc[2 * s + 1][3]);
            }
        }
    }

    float p0[8], p1[8];
    #pragma unroll
    for (int o = 0; o < 8; o++) { p0[o] = 0.f; p1[o] = 0.f; }
    #pragma unroll
    for (int j = 0; j < 16; j++) {
        int col = 8 * j + 2 * (lane & 3);
        #pragma unroll
        for (int o = 0; o < 8; o++) {
            p0[o] += acc[j][0] * w3s[o][col] + acc[j][1] * w3s[o][col + 1];
            p1[o] += acc[j][2] * w3s[o][col] + acc[j][3] * w3s[o][col + 1];
        }
    }
    #pragma unroll
    for (int o = 0; o < 8; o++) {
        #pragma unroll
        for (int m = 1; m <= 2; m <<= 1) {
            p0[o] += __shfl_xor_sync(0xffffffffu, p0[o], m);
            p1[o] += __shfl_xor_sync(0xffffffffu, p1[o], m);
        }
    }
    int grow0 = bm + 16 * w + (lane >> 2);
    int grow1 = grow0 + 8;
    int k2 = lane & 3;
    float b30 = b3[2 * k2], b31 = b3[2 * k2 + 1];
    *(float2*)&PHI[(size_t)grow0 * MODEN + 2 * k2] = make_float2(p0[2 * k2] + b30, p0[2 * k2 + 1] + b31);
    *(float2*)&PHI[(size_t)grow1 * MODEN + 2 * k2] = make_float2(p1[2 * k2] + b30, p1[2 * k2 + 1] + b31);
}

// ---------------- fp16 flash attention, 128-key tiles, log2-domain softmax (R14 proven) ----------------
__global__ __launch_bounds__(256) void attn_mma_kernel(const __half* __restrict__ QKV,
                                                       __half* __restrict__ CTX) {
    int h = blockIdx.y;
    int b = blockIdx.z;
    int qbase = blockIdx.x * 128;
    int t = threadIdx.x;
    int w = t >> 5, lane = t & 31;

    __shared__ __half Qs[128][40];
    __shared__ __half Ks[128][40];
    __shared__ __half Vs[128][40];

    const __half* base = QKV + (size_t)b * (LL * 384);

    #pragma unroll
    for (int i = 0; i < 2; i++) {
        int idx = t + i * 256;
        int row = idx >> 2;
        int c8  = (idx & 3) * 8;
        *(uint4*)&Qs[row][c8] =
            *(const uint4*)(base + (size_t)(qbase + row) * 384 + h * 32 + c8);
    }

    int tt = t & 127;
    int koff = (t < 128) ? 128 : 256;
    uint4 pf[4];
    {
        const uint4* s = (const uint4*)(base + (size_t)tt * 384 + koff + h * 32);
        pf[0] = s[0]; pf[1] = s[1]; pf[2] = s[2]; pf[3] = s[3];
    }
    __syncthreads();

    uint32_t qa[2][4];
    {
        int qr = w * 16;
        #pragma unroll
        for (int s = 0; s < 2; s++) {
            int row = qr + (lane & 15);
            int col = s * 16 + (lane >> 4) * 8;
            LDSM4(qa[s][0], qa[s][1], qa[s][2], qa[s][3], smem_u32(&Qs[row][col]));
        }
    }

    float oacc[4][4];
    #pragma unroll
    for (int j = 0; j < 4; j++)
        #pragma unroll
        for (int c = 0; c < 4; c++) oacc[j][c] = 0.f;
    float mrun0 = -1e30f, mrun1 = -1e30f, l0 = 0.f, l1 = 0.f;

    for (int kt = 0; kt < 8; kt++) {
        {
            uint4* d = (uint4*)&((t < 128) ? Ks : Vs)[tt][0];
            d[0] = pf[0]; d[1] = pf[1]; d[2] = pf[2]; d[3] = pf[3];
        }
        __syncthreads();
        if (kt < 7) {
            const uint4* s = (const uint4*)(base + (size_t)((kt + 1) * 128 + tt) * 384 + koff + h * 32);
            pf[0] = s[0]; pf[1] = s[1]; pf[2] = s[2]; pf[3] = s[3];
        }

        float sacc[16][4];
        #pragma unroll
        for (int j = 0; j < 16; j++)
            #pragma unroll
            for (int c = 0; c < 4; c++) sacc[j][c] = 0.f;

        #pragma unroll
        for (int j = 0; j < 16; j++) {
            uint32_t kb[4];
            uint32_t addr = smem_u32(&Ks[8 * j + (lane & 7)][(lane >> 3) * 8]);
            LDSM4(kb[0], kb[1], kb[2], kb[3], addr);
            MMA16816(sacc[j], qa[0][0], qa[0][1], qa[0][2], qa[0][3], kb[0], kb[1]);
            MMA16816(sacc[j], qa[1][0], qa[1][1], qa[1][2], qa[1][3], kb[2], kb[3]);
        }

        float mx0 = -1e30f, mx1 = -1e30f;
        #pragma unroll
        for (int j = 0; j < 16; j++) {
            mx0 = fmaxf(mx0, fmaxf(sacc[j][0], sacc[j][1]));
            mx1 = fmaxf(mx1, fmaxf(sacc[j][2], sacc[j][3]));
        }
        #pragma unroll
        for (int o = 1; o <= 2; o <<= 1) {
            mx0 = fmaxf(mx0, __shfl_xor_sync(0xffffffffu, mx0, o));
            mx1 = fmaxf(mx1, __shfl_xor_sync(0xffffffffu, mx1, o));
        }
        float nm0 = fmaxf(mrun0, mx0), nm1 = fmaxf(mrun1, mx1);
        float al0 = ex2f(mrun0 - nm0), al1 = ex2f(mrun1 - nm1);
        mrun0 = nm0; mrun1 = nm1;

        float rs0 = 0.f, rs1 = 0.f;
        #pragma unroll
        for (int j = 0; j < 16; j++) {
            sacc[j][0] = ex2f(sacc[j][0] - nm0); rs0 += sacc[j][0];
            sacc[j][1] = ex2f(sacc[j][1] - nm0); rs0 += sacc[j][1];
            sacc[j][2] = ex2f(sacc[j][2] - nm1); rs1 += sacc[j][2];
            sacc[j][3] = ex2f(sacc[j][3] - nm1); rs1 += sacc[j][3];
        }
        #pragma unroll
        for (int o = 1; o <= 2; o <<= 1) {
            rs0 += __shfl_xor_sync(0xffffffffu, rs0, o);
            rs1 += __shfl_xor_sync(0xffffffffu, rs1, o);
        }
        l0 = l0 * al0 + rs0;
        l1 = l1 * al1 + rs1;
        #pragma unroll
        for (int j = 0; j < 4; j++) {
            oacc[j][0] *= al0; oacc[j][1] *= al0;
            oacc[j][2] *= al1; oacc[j][3] *= al1;
        }

        #pragma unroll
        for (int s = 0; s < 8; s++) {
            uint32_t pa0 = f2h2(sacc[2 * s][0], sacc[2 * s][1]);
            uint32_t pa1 = f2h2(sacc[2 * s][2], sacc[2 * s][3]);
            uint32_t pa2 = f2h2(sacc[2 * s + 1][0], sacc[2 * s + 1][1]);
            uint32_t pa3 = f2h2(sacc[2 * s + 1][2], sacc[2 * s + 1][3]);
            #pragma unroll
            for (int jj = 0; jj < 2; jj++) {
                uint32_t vb[4];
                uint32_t addr = smem_u32(&Vs[16 * s + (lane & 15)][8 * (2 * jj + (lane >> 4))]);
                LDSM4T(vb[0], vb[1], vb[2], vb[3], addr);
                MMA16816(oacc[2 * jj],     pa0, pa1, pa2, pa3, vb[0], vb[1]);
                MMA16816(oacc[2 * jj + 1], pa0, pa1, pa2, pa3, vb[2], vb[3]);
            }
        }
        __syncthreads();
    }

    float inv0 = 1.f / l0, inv1 = 1.f / l1;
    int r0 = qbase + w * 16 + (lane >> 2);
    __half* o0 = CTX + ((size_t)(b * LL + r0)) * DIMD + h * 32 + 2 * (lane & 3);
    __half* o1 = o0 + 8 * DIMD;
    #pragma unroll
    for (int j = 0; j < 4; j++) {
        *(__half2*)(o0 + 8 * j) = __floats2half2_rn(oacc[j][0] * inv0, oacc[j][1] * inv0);
        *(__half2*)(o1 + 8 * j) = __floats2half2_rn(oacc[j][2] * inv1, oacc[j][3] * inv1);
    }
}

// ---------------- fused per-batch maxabs + normalize ----------------
__global__ void norm_kernel(const float* __restrict__ phi, float* __restrict__ out) {
    int b = blockIdx.x;
    int n = threadIdx.x; // 256
    __shared__ float sm[256][8];
    float v[8];
    #pragma unroll
    for (int j = 0; j < 8; j++) {
        v[j] = phi[((size_t)b * NN + n) * MODEN + j];
        sm[n][j] = fabsf(v[j]);
    }
    __syncthreads();
    for (int s = 128; s > 0; s >>= 1) {
        if (n < s) {
            #pragma unroll
            for (int j = 0; j < 8; j++) sm[n][j] = fmaxf(sm[n][j], sm[n + s][j]);
        }
        __syncthreads();
    }
    #pragma unroll
    for (int j = 0; j < 8; j++)
        out[((size_t)b * NN + n) * MODEN + j] = v[j] / sm[0][j];
}

// ---------------- launch ----------------
extern "C" void kernel_launch(void* const* d_in, const int* in_sizes, int n_in,
                              void* d_out, int out_size) {
    (void)in_sizes; (void)n_in; (void)out_size;
    const float* acc_Y      = (const float*)d_in[0];
    const float* proj_in_w  = (const float*)d_in[2];
    const float* proj_in_b  = (const float*)d_in[3];
    const float* attn_in_w  = (const float*)d_in[4];
    const float* attn_in_b  = (const float*)d_in[5];
    const float* attn_out_w = (const float*)d_in[6];
    const float* attn_out_b = (const float*)d_in[7];
    const float* ln1_g      = (const float*)d_in[8];
    const float* ln1_b      = (const float*)d_in[9];
    const float* ff1_w      = (const float*)d_in[10];
    const float* ff1_b      = (const float*)d_in[11];
    const float* ff2_w      = (const float*)d_in[12];
    const float* ff2_b      = (const float*)d_in[13];
    const float* ln2_g      = (const float*)d_in[14];
    const float* ln2_b      = (const float*)d_in[15];
    const float* proj_out_w = (const float*)d_in[16];
    const float* proj_out_b = (const float*)d_in[17];
    const float* mlp1_w     = (const float*)d_in[18];
    const float* mlp1_b     = (const float*)d_in[19];
    const float* mlp2_w     = (const float*)d_in[20];
    const float* mlp2_b     = (const float*)d_in[21];
    const float* mlp3_w     = (const float*)d_in[22];
    const float* mlp3_b     = (const float*)d_in[23];
    float* out = (float*)d_out;

    float  *pX, *pX2, *pPHI, *pABb;
    __half *pXh, *pX2h, *pQKVh, *pCTXh, *pTMPh, *pWh;
    cudaGetSymbolAddress((void**)&pX,    g_X);
    cudaGetSymbolAddress((void**)&pXh,   g_Xh);
    cudaGetSymbolAddress((void**)&pX2,   g_X2);
    cudaGetSymbolAddress((void**)&pX2h,  g_X2h);
    cudaGetSymbolAddress((void**)&pQKVh, g_QKVh);
    cudaGetSymbolAddress((void**)&pCTXh, g_CTXh);
    cudaGetSymbolAddress((void**)&pTMPh, g_TMPh);
    cudaGetSymbolAddress((void**)&pPHI,  g_PHI);
    cudaGetSymbolAddress((void**)&pWh,   g_Wh);
    cudaGetSymbolAddress((void**)&pABb,  g_ABb);

    convw_kernel<<<W_TOTAL / 256, 256>>>(attn_in_w, attn_out_w, ff1_w, ff2_w, mlp1_w, mlp2_w, pWh);
    biasq_kernel<<<2, 192>>>(attn_in_b, pABb);

    // ===== q path =====
    proj_in_kernel<<<MQ, 128>>>(acc_Y, proj_in_w, proj_in_b, pX, pXh);
    hgemm_kernel<0,1><<<dim3(6, MQ / 128), 256>>>(pXh, pWh + W_ATTNIN, pABb, pQKVh, MQ, 384, 128);
    attn_mma_kernel<<<dim3(LL / 128, HH, BB), 256>>>(pQKVh, pCTXh);
    hgemm_ln_kernel<0><<<MQ / 128, 256>>>(pCTXh, pWh + W_ATTNOUT, attn_out_b, pX, ln1_g, ln1_b,
                                          pX2, pX2h, nullptr, nullptr, nullptr, MQ, 128);
    hgemm_kernel<1,1><<<dim3(4, MQ / 128), 256>>>(pX2h, pWh + W_FF1, ff1_b, pTMPh, MQ, 256, 128);
    hgemm_ln_kernel<1><<<MQ / 128, 256>>>(pTMPh, pWh + W_FF2, ff2_b, pX2, ln2_g, ln2_b,
                                          nullptr, nullptr, proj_out_w, proj_out_b, out, MQ, 256);

    // ===== phi path (fused) =====
    phi_fused_kernel<<<MP / 128, 256>>>(acc_Y, pWh + W_MLP1, mlp1_b, pWh + W_MLP2, mlp2_b,
                                        mlp3_w, mlp3_b, pPHI);
    norm_kernel<<<BB, 256>>>(pPHI, out + MQ * MODEN);
}